// round 12
// baseline (speedup 1.0000x reference)
#include <cuda_runtime.h>
#include <cstdint>
#include <cstddef>

namespace {
constexpr int kB = 16, kS = 2048, kD = 128, TQ = 64, TK = 64, NT = 256;
constexpr int NKT = kS / TK;   // 32
constexpr int QP = 132;        // Q pitch (floats)
constexpr int KP = 132;        // K pitch
constexpr int VTP = 76;        // V^T pitch: 12*l mod 32 -> conflict-free staging
constexpr int PP = 68;         // P pitch
constexpr float kScale = 0.08838834764831845f;  // 1/sqrt(128)

struct Smem {
  float Qs[TQ * QP];                                   // 33.8 KB
  union { float Ks[TK * KP]; float VT[kD * VTP]; } kv; // 38.0 KB (union)
  float Ps[TQ * PP];                                   // 17.4 KB
  float Zs[TQ];
  float rZs[TQ];
  float Zp[2][TQ];
  float Vps[2][kD];
  float Vcsum[kD];
};
constexpr int SMEM_BYTES = (int)sizeof(Smem);          // ~91 KB -> 2 CTAs/SM

__device__ __forceinline__ uint32_t f2tf32(float f) {
  uint32_t u; asm("cvt.rna.tf32.f32 %0, %1;" : "=r"(u) : "f"(f)); return u;
}
__device__ __forceinline__ float tff(float f) { return __uint_as_float(f2tf32(f)); }

__device__ __forceinline__ void ldm_x4(uint32_t& r0, uint32_t& r1,
                                       uint32_t& r2, uint32_t& r3, uint32_t a) {
  asm volatile("ldmatrix.sync.aligned.m8n8.x4.shared.b16 {%0,%1,%2,%3}, [%4];"
               : "=r"(r0), "=r"(r1), "=r"(r2), "=r"(r3) : "r"(a));
}
__device__ __forceinline__ void mma_tf32(float c[4], uint32_t a0, uint32_t a1,
                                         uint32_t a2, uint32_t a3,
                                         uint32_t b0, uint32_t b1) {
  asm volatile(
      "mma.sync.aligned.m16n8k8.row.col.f32.tf32.tf32.f32 "
      "{%0,%1,%2,%3}, {%4,%5,%6,%7}, {%8,%9}, {%0,%1,%2,%3};\n"
      : "+f"(c[0]), "+f"(c[1]), "+f"(c[2]), "+f"(c[3])
      : "r"(a0), "r"(a1), "r"(a2), "r"(a3), "r"(b0), "r"(b1));
}
}  // namespace

extern "C" __global__ void __launch_bounds__(NT, 2)
sdpa_kernel(const float* __restrict__ Q, const float* __restrict__ K,
            const float* __restrict__ V, float* __restrict__ out,
            float* __restrict__ attn)
{
  extern __shared__ char smem_raw[];
  Smem& sm = *reinterpret_cast<Smem*>(smem_raw);

  const int qt  = blockIdx.x;
  const int b   = blockIdx.y;
  const int tid = threadIdx.x;
  const int q0  = qt * TQ;
  const int wid  = tid >> 5;        // 0..7
  const int lane = tid & 31;
  const int wr   = wid >> 1;        // 0..3 (16-row band)
  const int wc   = wid & 1;         // 0..1 (32 QK cols / 64 PV d-cols)
  const int gid  = lane >> 2;       // 0..7
  const int tig  = lane & 3;        // 0..3
  const int r0 = 16 * wr + gid, r1 = r0 + 8;
  const int rg0 = q0 + r0, rg1 = q0 + r1;

  const float* Qb = Q + (size_t)b * kS * kD;
  const float* Kb = K + (size_t)b * kS * kD;
  const float* Vb = V + (size_t)b * kS * kD;
  float* outb  = out  + (size_t)b * kS * kD;
  float* attnb = attn + (size_t)b * kS * kS;

  const uint32_t smQ  = (uint32_t)__cvta_generic_to_shared(sm.Qs);
  const uint32_t smK  = (uint32_t)__cvta_generic_to_shared(sm.kv.Ks);
  const uint32_t smVT = (uint32_t)__cvta_generic_to_shared(sm.kv.VT);
  const uint32_t smP  = (uint32_t)__cvta_generic_to_shared(sm.Ps);

  // ldmatrix per-thread base addresses (layouts verified in R10/R11)
  const uint32_t qa_base = smQ + (uint32_t)((16 * wr + (lane & 15)) * QP * 4 + (lane >> 4) * 16);
  const uint32_t pa_base = smP + (uint32_t)((16 * wr + (lane & 15)) * PP * 4 + (lane >> 4) * 16);
  const uint32_t kb_base = smK + (uint32_t)((32 * wc + (lane & 7) + 8 * (lane >> 4)) * KP * 4 +
                                            ((lane >> 3) & 1) * 16);
  const uint32_t vb_base = smVT + (uint32_t)((64 * wc + (lane & 7) + 8 * (lane >> 4)) * VTP * 4 +
                                             ((lane >> 3) & 1) * 16);

  // ---- stage Q (tf32, once): 64 rows x 32 float4 ----
  {
    const float4* Qg = reinterpret_cast<const float4*>(Qb + (size_t)q0 * kD);
#pragma unroll
    for (int j = 0; j < 8; ++j) {
      const int f = tid + j * NT;
      const int r = f >> 5;
      float4 v = Qg[f];
      float4 t = make_float4(tff(v.x), tff(v.y), tff(v.z), tff(v.w));
      *reinterpret_cast<float4*>(&sm.Qs[r * QP + (f & 31) * 4]) = t;
    }
  }
  if (tid < TQ) sm.Zs[tid] = (float)q0;   // lower-region masked ones

  // V staging assignment: thread owns d-col vd, tokens 32*vhalf..+32
  const int vd    = tid & 127;
  const int vhalf = tid >> 7;

  // prefetch first K tile
  float4 kreg[8];
  {
    const float4* Kg = reinterpret_cast<const float4*>(Kb + (size_t)qt * TK * kD);
#pragma unroll
    for (int j = 0; j < 8; ++j) kreg[j] = Kg[tid + j * NT];
  }

  float oacc[8][4];
#pragma unroll
  for (int j = 0; j < 8; ++j)
#pragma unroll
    for (int v = 0; v < 4; ++v) oacc[j][v] = 0.f;

  // ================= Phase 1 =================
  for (int kt = qt; kt < NKT; ++kt) {
    const int k0 = kt * TK;
    __syncthreads();   // [1] prev PV reads of kv/Ps done; Q/Zs ready on i=0

    // stage K (tf32) into union buffer
#pragma unroll
    for (int j = 0; j < 8; ++j) {
      const int f = tid + j * NT;
      const int r = f >> 5;
      float4 t = make_float4(tff(kreg[j].x), tff(kreg[j].y),
                             tff(kreg[j].z), tff(kreg[j].w));
      *reinterpret_cast<float4*>(&sm.kv.Ks[r * KP + (f & 31) * 4]) = t;
    }
    __syncthreads();   // [2] Ks visible

    // ---- QK^T: rows 16wr..+16, cols 32wc..+32 ----
    float sacc[4][4];
#pragma unroll
    for (int j = 0; j < 4; ++j)
#pragma unroll
      for (int v = 0; v < 4; ++v) sacc[j][v] = 0.f;
#pragma unroll
    for (int s = 0; s < 16; ++s) {
      uint32_t a0, a1, a2, a3, b0, b1, b2, b3, c0, c1, c2, c3;
      ldm_x4(a0, a1, a2, a3, qa_base + (uint32_t)(s * 32));
      ldm_x4(b0, b1, b2, b3, kb_base + (uint32_t)(s * 32));
      ldm_x4(c0, c1, c2, c3, kb_base + (uint32_t)(16 * KP * 4 + s * 32));
      mma_tf32(sacc[0], a0, a1, a2, a3, b0, b1);
      mma_tf32(sacc[1], a0, a1, a2, a3, b2, b3);
      mma_tf32(sacc[2], a0, a1, a2, a3, c0, c1);
      mma_tf32(sacc[3], a0, a1, a2, a3, c2, c3);
    }

    // V gmem loads for this tile (latency covered by exp below)
    float vreg[32];
    {
      const float* Vg = Vb + (size_t)k0 * kD;
#pragma unroll
      for (int i = 0; i < 32; ++i)
        vreg[i] = Vg[(size_t)(32 * vhalf + i) * kD + vd];
    }

    // ---- mask + exp; attn store; Ps store; Z partials ----
    const bool diag = (kt == qt);
    float rs0 = 0.f, rs1 = 0.f;
    float* arow0 = attnb + (size_t)rg0 * kS + k0;
    float* arow1 = attnb + (size_t)rg1 * kS + k0;
#pragma unroll
    for (int j = 0; j < 4; ++j) {
      const int c = 32 * wc + 8 * j + 2 * tig;
      float e00, e01, e10, e11;
      if (diag) {
        e00 = (c     > r0) ? __expf(sacc[j][0] * kScale) : 1.0f;
        e01 = (c + 1 > r0) ? __expf(sacc[j][1] * kScale) : 1.0f;
        e10 = (c     > r1) ? __expf(sacc[j][2] * kScale) : 1.0f;
        e11 = (c + 1 > r1) ? __expf(sacc[j][3] * kScale) : 1.0f;
      } else {
        e00 = __expf(sacc[j][0] * kScale);
        e01 = __expf(sacc[j][1] * kScale);
        e10 = __expf(sacc[j][2] * kScale);
        e11 = __expf(sacc[j][3] * kScale);
      }
      rs0 += e00 + e01;   // masked 1.0s included; Z init = q0 covers lower region
      rs1 += e10 + e11;
      *reinterpret_cast<float2*>(arow0 + c) = make_float2(e00, e01);
      *reinterpret_cast<float2*>(arow1 + c) = make_float2(e10, e11);
      *reinterpret_cast<float2*>(&sm.Ps[r0 * PP + c]) = make_float2(tff(e00), tff(e01));
      *reinterpret_cast<float2*>(&sm.Ps[r1 * PP + c]) = make_float2(tff(e10), tff(e11));
    }
    rs0 += __shfl_xor_sync(0xffffffffu, rs0, 1, 4);
    rs0 += __shfl_xor_sync(0xffffffffu, rs0, 2, 4);
    rs1 += __shfl_xor_sync(0xffffffffu, rs1, 1, 4);
    rs1 += __shfl_xor_sync(0xffffffffu, rs1, 2, 4);
    if (tig == 0) { sm.Zp[wc][r0] = rs0; sm.Zp[wc][r1] = rs1; }
    __syncthreads();   // [3] QK reads of kv done; Ps + Zp visible
    if (tid < TQ) sm.Zs[tid] += sm.Zp[0][tid] + sm.Zp[1][tid];

    // stage V^T (tf32) into union buffer (conflict-free: VTP=76)
#pragma unroll
    for (int m = 0; m < 8; ++m) {
      float4 t = make_float4(tff(vreg[4 * m + 0]), tff(vreg[4 * m + 1]),
                             tff(vreg[4 * m + 2]), tff(vreg[4 * m + 3]));
      *reinterpret_cast<float4*>(&sm.kv.VT[vd * VTP + 32 * vhalf + 4 * m]) = t;
    }
    // prefetch next K (covered by PV)
    if (kt + 1 < NKT) {
      const float4* Kg = reinterpret_cast<const float4*>(Kb + (size_t)(k0 + TK) * kD);
#pragma unroll
      for (int j = 0; j < 8; ++j) kreg[j] = Kg[tid + j * NT];
    }
    __syncthreads();   // [4] VT visible

    // ---- PV: rows 16wr..+16, out d-cols 64wc..+64 ----
#pragma unroll
    for (int kk = 0; kk < 8; ++kk) {
      uint32_t a0, a1, a2, a3;
      ldm_x4(a0, a1, a2, a3, pa_base + (uint32_t)(kk * 32));
#pragma unroll
      for (int t = 0; t < 4; ++t) {
        uint32_t b0, b1, b2, b3;
        ldm_x4(b0, b1, b2, b3, vb_base + (uint32_t)(t * 16 * VTP * 4 + kk * 32));
        mma_tf32(oacc[2 * t + 0], a0, a1, a2, a3, b0, b1);
        mma_tf32(oacc[2 * t + 1], a0, a1, a2, a3, b2, b3);
      }
    }
  }

  // ================= Phase 2 =================
  __syncthreads();
  if (tid < TQ) sm.rZs[tid] = 1.0f / sm.Zs[tid];
  __syncthreads();

  // lower-region V column sums (deterministic, 4-way MLP)
  {
    const int vc = tid & 127, vq = tid >> 7;   // 2 residue groups
    float a0 = 0.f, a1 = 0.f, a2 = 0.f, a3 = 0.f;
    for (int t = vq; t < q0; t += 8) {
      a0 += Vb[(size_t)t * kD + vc];
      a1 += Vb[(size_t)(t + 2) * kD + vc];
      a2 += Vb[(size_t)(t + 4) * kD + vc];
      a3 += Vb[(size_t)(t + 6) * kD + vc];
    }
    sm.Vps[vq][vc] = (a0 + a1) + (a2 + a3);
  }

  // lower attn fill = 1/Z (64 rows x 16 float4 per k-tile)
  const int ftr = tid >> 4, ftc = tid & 15;   // 16 row-slots
  for (int kt = 0; kt < qt; ++kt) {
    const int k0 = kt * TK;
#pragma unroll
    for (int p = 0; p < 4; ++p) {
      const int r = ftr + 16 * p;
      const float rz = sm.rZs[r];
      *reinterpret_cast<float4*>(&attnb[(size_t)(q0 + r) * kS + k0 + 4 * ftc]) =
          make_float4(rz, rz, rz, rz);
    }
  }
  __syncthreads();
  if (tid < kD) sm.Vcsum[tid] = sm.Vps[0][tid] + sm.Vps[1][tid];
  __syncthreads();

  // rescale upper attn tiles: attn *= 1/Z (4 rows in flight)
  {
    const float rzA = sm.rZs[ftr];
    const float rzB = sm.rZs[ftr + 16];
    const float rzC = sm.rZs[ftr + 32];
    const float rzD = sm.rZs[ftr + 48];
    for (int kt = qt; kt < NKT; ++kt) {
      const int k0 = kt * TK;
      float4* pA = reinterpret_cast<float4*>(&attnb[(size_t)(q0 + ftr)      * kS + k0 + 4 * ftc]);
      float4* pB = reinterpret_cast<float4*>(&attnb[(size_t)(q0 + ftr + 16) * kS + k0 + 4 * ftc]);
      float4* pC = reinterpret_cast<float4*>(&attnb[(size_t)(q0 + ftr + 32) * kS + k0 + 4 * ftc]);
      float4* pD = reinterpret_cast<float4*>(&attnb[(size_t)(q0 + ftr + 48) * kS + k0 + 4 * ftc]);
      float4 vA = *pA, vB = *pB, vC = *pC, vD = *pD;
      vA.x *= rzA; vA.y *= rzA; vA.z *= rzA; vA.w *= rzA;
      vB.x *= rzB; vB.y *= rzB; vB.z *= rzB; vB.w *= rzB;
      vC.x *= rzC; vC.y *= rzC; vC.z *= rzC; vC.w *= rzC;
      vD.x *= rzD; vD.y *= rzD; vD.z *= rzD; vD.w *= rzD;
      *pA = vA; *pB = vB; *pC = vC; *pD = vD;
    }
  }

  // final output: rows rg0/rg1, d-cols 64wc + 8jj + 2tig
  {
    const float rz0 = sm.rZs[r0], rz1 = sm.rZs[r1];
#pragma unroll
    for (int jj = 0; jj < 8; ++jj) {
      const int c = 64 * wc + 8 * jj + 2 * tig;
      const float vs0 = sm.Vcsum[c], vs1 = sm.Vcsum[c + 1];
      float2 o0 = make_float2(rz0 * (oacc[jj][0] + vs0), rz0 * (oacc[jj][1] + vs1));
      float2 o1 = make_float2(rz1 * (oacc[jj][2] + vs0), rz1 * (oacc[jj][3] + vs1));
      *reinterpret_cast<float2*>(&outb[(size_t)rg0 * kD + c]) = o0;
      *reinterpret_cast<float2*>(&outb[(size_t)rg1 * kD + c]) = o1;
    }
  }
}

extern "C" void kernel_launch(void* const* d_in, const int* in_sizes, int n_in,
                              void* d_out, int out_size) {
  (void)in_sizes; (void)n_in; (void)out_size;
  const float* Q = (const float*)d_in[0];
  const float* K = (const float*)d_in[1];
  const float* V = (const float*)d_in[2];
  float* out  = (float*)d_out;
  float* attn = out + (size_t)kB * kS * kD;

  cudaFuncSetAttribute(sdpa_kernel, cudaFuncAttributeMaxDynamicSharedMemorySize,
                       SMEM_BYTES);
  dim3 grid(NKT, kB);   // heavy q-tiles first
  sdpa_kernel<<<grid, NT, SMEM_BYTES>>>(Q, K, V, out, attn);
}

// round 13
// speedup vs baseline: 1.0213x; 1.0213x over previous
#include <cuda_runtime.h>
#include <cstdint>
#include <cstddef>

namespace {
constexpr int kB = 16, kS = 2048, kD = 128, TQ = 64, TK = 64, NT = 512;
constexpr int NKT = kS / TK;   // 32
constexpr int QP = 132;        // Q pitch (floats)
constexpr int KP = 132;        // K pitch
constexpr int VTP = 68;        // V^T pitch ([d=128][tok=64])
constexpr int PP = 68;         // P pitch

struct Smem {
  float Qs[TQ * QP];       // 33.8 KB tf32
  float Ks[TK * KP];       // 33.8 KB tf32
  float VT[kD * VTP];      // 34.8 KB tf32, transposed [d][tok]
  float Ps[TQ * PP];       // 17.4 KB tf32
  float Zs[TQ];
  float rZs[TQ];
  float Zp[4][TQ];
  float Vps[4][kD];
  float Vcsum[kD];
};
constexpr int SMEM_BYTES = (int)sizeof(Smem);

// exp(s * 1/sqrt(128)) = 2^(s * C), C = kScale * log2(e)
constexpr float kC = 0.12752991043f;

__device__ __forceinline__ float exp_mufu(float s) {
  float y = s * kC, r;
  asm("ex2.approx.ftz.f32 %0, %1;" : "=f"(r) : "f"(y));
  return r;
}
// FFMA-pipe exp: magic-number split + deg-4 exp2 poly + exponent reassembly.
// Max rel err ~4e-5 on |y| <= 16 (we have |y| <~ 8).
__device__ __forceinline__ float exp_poly(float s) {
  float y = s * kC;
  float r = y + 12582912.0f;             // 1.5 * 2^23 round-to-nearest magic
  float f = y - (r - 12582912.0f);       // f in [-0.5, 0.5]
  int n = __float_as_int(r);             // low bits hold round(y)
  float p = 0.0096181f;
  p = fmaf(p, f, 0.0555042f);
  p = fmaf(p, f, 0.2402265f);
  p = fmaf(p, f, 0.6931472f);
  p = fmaf(p, f, 1.0f);
  return __int_as_float(__float_as_int(p) + (n << 23));
}

__device__ __forceinline__ uint32_t f2tf32(float f) {
  uint32_t u; asm("cvt.rna.tf32.f32 %0, %1;" : "=r"(u) : "f"(f)); return u;
}
__device__ __forceinline__ float tff(float f) { return __uint_as_float(f2tf32(f)); }

__device__ __forceinline__ void ldm_x4(uint32_t& r0, uint32_t& r1,
                                       uint32_t& r2, uint32_t& r3, uint32_t a) {
  asm volatile("ldmatrix.sync.aligned.m8n8.x4.shared.b16 {%0,%1,%2,%3}, [%4];"
               : "=r"(r0), "=r"(r1), "=r"(r2), "=r"(r3) : "r"(a));
}
__device__ __forceinline__ void mma_tf32(float c[4], uint32_t a0, uint32_t a1,
                                         uint32_t a2, uint32_t a3,
                                         uint32_t b0, uint32_t b1) {
  asm volatile(
      "mma.sync.aligned.m16n8k8.row.col.f32.tf32.tf32.f32 "
      "{%0,%1,%2,%3}, {%4,%5,%6,%7}, {%8,%9}, {%0,%1,%2,%3};\n"
      : "+f"(c[0]), "+f"(c[1]), "+f"(c[2]), "+f"(c[3])
      : "r"(a0), "r"(a1), "r"(a2), "r"(a3), "r"(b0), "r"(b1));
}
}  // namespace

extern "C" __global__ void __launch_bounds__(NT, 1)
sdpa_kernel(const float* __restrict__ Q, const float* __restrict__ K,
            const float* __restrict__ V, float* __restrict__ out,
            float* __restrict__ attn)
{
  extern __shared__ char smem_raw[];
  Smem& sm = *reinterpret_cast<Smem*>(smem_raw);

  const int qt  = blockIdx.x;
  const int b   = blockIdx.y;
  const int tid = threadIdx.x;
  const int q0  = qt * TQ;
  const int wid  = tid >> 5;        // 0..15
  const int lane = tid & 31;
  const int wr   = wid >> 2;        // 0..3 (16-row band)
  const int wc   = wid & 3;         // 0..3 (16 QK cols / 32 PV cols)
  const int gid  = lane >> 2;       // 0..7
  const int tig  = lane & 3;        // 0..3
  const int r0 = 16 * wr + gid, r1 = r0 + 8;

  const float* Qb = Q + (size_t)b * kS * kD;
  const float* Kb = K + (size_t)b * kS * kD;
  const float* Vb = V + (size_t)b * kS * kD;
  float* outb  = out  + (size_t)b * kS * kD;
  float* attnb = attn + (size_t)b * kS * kS;

  const uint32_t smQ  = (uint32_t)__cvta_generic_to_shared(sm.Qs);
  const uint32_t smK  = (uint32_t)__cvta_generic_to_shared(sm.Ks);
  const uint32_t smVT = (uint32_t)__cvta_generic_to_shared(sm.VT);
  const uint32_t smP  = (uint32_t)__cvta_generic_to_shared(sm.Ps);

  const uint32_t qa_base = smQ + (uint32_t)((16 * wr + (lane & 15)) * QP * 4 + (lane >> 4) * 16);
  const uint32_t pa_base = smP + (uint32_t)((16 * wr + (lane & 15)) * PP * 4 + (lane >> 4) * 16);
  const uint32_t kb_base = smK + (uint32_t)((16 * wc + (lane & 7) + 8 * (lane >> 4)) * KP * 4 +
                                            ((lane >> 3) & 1) * 16);
  const uint32_t vb_base = smVT + (uint32_t)((32 * wc + (lane & 7) + 8 * (lane >> 4)) * VTP * 4 +
                                             ((lane >> 3) & 1) * 16);

  // ---- stage Q (tf32, once) ----
  {
    const float4* Qg = reinterpret_cast<const float4*>(Qb + (size_t)q0 * kD);
#pragma unroll
    for (int j = 0; j < 4; ++j) {
      const int f = tid + j * NT;
      const int r = f >> 5;
      float4 v = Qg[f];
      float4 t = make_float4(tff(v.x), tff(v.y), tff(v.z), tff(v.w));
      *reinterpret_cast<float4*>(&sm.Qs[r * QP + lane * 4]) = t;
    }
  }
  if (tid < TQ) sm.Zs[tid] = (float)q0;

  // ---- prefetch first K/V tile into registers ----
  float4 kreg[4];
  float vreg[16];
  const int vd = 32 * (wid & 3) + lane;   // d column this thread handles
  const int vt0 = 4 * (wid >> 2);         // base token
  {
    const float4* Kg = reinterpret_cast<const float4*>(Kb + (size_t)qt * TK * kD);
#pragma unroll
    for (int j = 0; j < 4; ++j) kreg[j] = Kg[tid + j * NT];
    const float* Vg = Vb + (size_t)qt * TK * kD;
#pragma unroll
    for (int j = 0; j < 4; ++j)
#pragma unroll
      for (int t = 0; t < 4; ++t)
        vreg[4 * j + t] = Vg[(size_t)(vt0 + 16 * j + t) * kD + vd];
  }

  float oacc[4][4];
#pragma unroll
  for (int j = 0; j < 4; ++j)
#pragma unroll
    for (int v = 0; v < 4; ++v) oacc[j][v] = 0.f;

  // ================= Phase 1: upper (incl diagonal) tiles =================
  for (int kt = qt; kt < NKT; ++kt) {
    const int k0 = kt * TK;
    __syncthreads();

    // ---- stage K (tf32) ----
#pragma unroll
    for (int j = 0; j < 4; ++j) {
      const int f = tid + j * NT;
      const int r = f >> 5;
      float4 t = make_float4(tff(kreg[j].x), tff(kreg[j].y),
                             tff(kreg[j].z), tff(kreg[j].w));
      *reinterpret_cast<float4*>(&sm.Ks[r * KP + lane * 4]) = t;
    }
    // ---- stage V transposed (tf32): VT[d][tok] ----
#pragma unroll
    for (int j = 0; j < 4; ++j) {
      float4 t = make_float4(tff(vreg[4 * j + 0]), tff(vreg[4 * j + 1]),
                             tff(vreg[4 * j + 2]), tff(vreg[4 * j + 3]));
      *reinterpret_cast<float4*>(&sm.VT[vd * VTP + vt0 + 16 * j]) = t;
    }
    // prefetch next tile
    if (kt + 1 < NKT) {
      const float4* Kg = reinterpret_cast<const float4*>(Kb + (size_t)(k0 + TK) * kD);
#pragma unroll
      for (int j = 0; j < 4; ++j) kreg[j] = Kg[tid + j * NT];
      const float* Vg = Vb + (size_t)(k0 + TK) * kD;
#pragma unroll
      for (int j = 0; j < 4; ++j)
#pragma unroll
        for (int t = 0; t < 4; ++t)
          vreg[4 * j + t] = Vg[(size_t)(vt0 + 16 * j + t) * kD + vd];
    }
    __syncthreads();

    // ---- QK^T ----
    float sacc[2][4];
#pragma unroll
    for (int j = 0; j < 2; ++j)
#pragma unroll
      for (int v = 0; v < 4; ++v) sacc[j][v] = 0.f;
#pragma unroll
    for (int s = 0; s < 16; ++s) {
      uint32_t a0, a1, a2, a3, b0, b1, b2, b3;
      ldm_x4(a0, a1, a2, a3, qa_base + (uint32_t)(s * 32));
      ldm_x4(b0, b1, b2, b3, kb_base + (uint32_t)(s * 32));
      mma_tf32(sacc[0], a0, a1, a2, a3, b0, b1);
      mma_tf32(sacc[1], a0, a1, a2, a3, b2, b3);
    }

    // ---- mask + exp (hybrid MUFU/poly); attn store; Ps store; Z partials ----
    const bool diag = (kt == qt);
    float rs0 = 0.f, rs1 = 0.f;
    float* arow0 = attnb + (size_t)(q0 + r0) * kS + k0;
    float* arow1 = attnb + (size_t)(q0 + r1) * kS + k0;
#pragma unroll
    for (int j = 0; j < 2; ++j) {
      const int c = 16 * wc + 8 * j + 2 * tig;
      // j==0: all MUFU; j==1: rows r1 via FFMA-poly (25% of exps off MUFU pipe)
      float x00, x01, x10, x11;
      x00 = exp_mufu(sacc[j][0]);
      x01 = exp_mufu(sacc[j][1]);
      if (j == 1) {
        x10 = exp_poly(sacc[j][2]);
        x11 = exp_poly(sacc[j][3]);
      } else {
        x10 = exp_mufu(sacc[j][2]);
        x11 = exp_mufu(sacc[j][3]);
      }
      float e00, e01, e10, e11;
      if (diag) {
        e00 = (c     > r0) ? x00 : 1.0f;
        e01 = (c + 1 > r0) ? x01 : 1.0f;
        e10 = (c     > r1) ? x10 : 1.0f;
        e11 = (c + 1 > r1) ? x11 : 1.0f;
      } else {
        e00 = x00; e01 = x01; e10 = x10; e11 = x11;
      }
      rs0 += e00 + e01;
      rs1 += e10 + e11;
      *reinterpret_cast<float2*>(arow0 + c) = make_float2(e00, e01);
      *reinterpret_cast<float2*>(arow1 + c) = make_float2(e10, e11);
      *reinterpret_cast<float2*>(&sm.Ps[r0 * PP + c]) = make_float2(tff(e00), tff(e01));
      *reinterpret_cast<float2*>(&sm.Ps[r1 * PP + c]) = make_float2(tff(e10), tff(e11));
    }
    rs0 += __shfl_xor_sync(0xffffffffu, rs0, 1, 4);
    rs0 += __shfl_xor_sync(0xffffffffu, rs0, 2, 4);
    rs1 += __shfl_xor_sync(0xffffffffu, rs1, 1, 4);
    rs1 += __shfl_xor_sync(0xffffffffu, rs1, 2, 4);
    if (tig == 0) { sm.Zp[wc][r0] = rs0; sm.Zp[wc][r1] = rs1; }
    __syncthreads();
    if (tid < TQ)
      sm.Zs[tid] += (sm.Zp[0][tid] + sm.Zp[1][tid]) +
                    (sm.Zp[2][tid] + sm.Zp[3][tid]);

    // ---- PV ----
#pragma unroll
    for (int kk = 0; kk < 8; ++kk) {
      uint32_t a0, a1, a2, a3;
      ldm_x4(a0, a1, a2, a3, pa_base + (uint32_t)(kk * 32));
#pragma unroll
      for (int t = 0; t < 2; ++t) {
        uint32_t b0, b1, b2, b3;
        ldm_x4(b0, b1, b2, b3,
               vb_base + (uint32_t)(t * 16 * VTP * 4 + kk * 32));
        mma_tf32(oacc[2 * t + 0], a0, a1, a2, a3, b0, b1);
        mma_tf32(oacc[2 * t + 1], a0, a1, a2, a3, b2, b3);
      }
    }
  }

  // ================= Phase 2 =================
  __syncthreads();
  if (tid < TQ) sm.rZs[tid] = 1.0f / sm.Zs[tid];
  __syncthreads();

  // lower-region V column sums (deterministic, 4-way MLP)
  {
    const int vc = tid & 127, vq = tid >> 7;
    float a0 = 0.f, a1 = 0.f, a2 = 0.f, a3 = 0.f;
    for (int t = vq; t < q0; t += 16) {
      a0 += Vb[(size_t)t * kD + vc];
      a1 += Vb[(size_t)(t + 4) * kD + vc];
      a2 += Vb[(size_t)(t + 8) * kD + vc];
      a3 += Vb[(size_t)(t + 12) * kD + vc];
    }
    sm.Vps[vq][vc] = (a0 + a1) + (a2 + a3);
  }

  // lower attn fill = 1/Z
  const int ftr = tid >> 4, ftc = tid & 15;   // 32 row-slots x 16 float4 cols
  for (int kt = 0; kt < qt; ++kt) {
    const int k0 = kt * TK;
#pragma unroll
    for (int p = 0; p < 2; ++p) {
      const int r = ftr + 32 * p;
      const float rz = sm.rZs[r];
      *reinterpret_cast<float4*>(&attnb[(size_t)(q0 + r) * kS + k0 + 4 * ftc]) =
          make_float4(rz, rz, rz, rz);
    }
  }
  __syncthreads();
  if (tid < kD)
    sm.Vcsum[tid] = (sm.Vps[0][tid] + sm.Vps[1][tid]) +
                    (sm.Vps[2][tid] + sm.Vps[3][tid]);
  __syncthreads();

  // rescale upper attn tiles (2 k-tiles in flight for MLP)
  {
    const float rzA = sm.rZs[ftr];
    const float rzB = sm.rZs[ftr + 32];
    int kt = qt;
    for (; kt + 1 < NKT; kt += 2) {
      float4* p00 = reinterpret_cast<float4*>(&attnb[(size_t)(q0 + ftr) * kS + kt * TK + 4 * ftc]);
      float4* p01 = reinterpret_cast<float4*>(&attnb[(size_t)(q0 + ftr + 32) * kS + kt * TK + 4 * ftc]);
      float4* p10 = reinterpret_cast<float4*>(&attnb[(size_t)(q0 + ftr) * kS + (kt + 1) * TK + 4 * ftc]);
      float4* p11 = reinterpret_cast<float4*>(&attnb[(size_t)(q0 + ftr + 32) * kS + (kt + 1) * TK + 4 * ftc]);
      float4 v00 = *p00, v01 = *p01, v10 = *p10, v11 = *p11;
      v00.x *= rzA; v00.y *= rzA; v00.z *= rzA; v00.w *= rzA;
      v01.x *= rzB; v01.y *= rzB; v01.z *= rzB; v01.w *= rzB;
      v10.x *= rzA; v10.y *= rzA; v10.z *= rzA; v10.w *= rzA;
      v11.x *= rzB; v11.y *= rzB; v11.z *= rzB; v11.w *= rzB;
      *p00 = v00; *p01 = v01; *p10 = v10; *p11 = v11;
    }
    if (kt < NKT) {
      float4* p00 = reinterpret_cast<float4*>(&attnb[(size_t)(q0 + ftr) * kS + kt * TK + 4 * ftc]);
      float4* p01 = reinterpret_cast<float4*>(&attnb[(size_t)(q0 + ftr + 32) * kS + kt * TK + 4 * ftc]);
      float4 v00 = *p00, v01 = *p01;
      v00.x *= rzA; v00.y *= rzA; v00.z *= rzA; v00.w *= rzA;
      v01.x *= rzB; v01.y *= rzB; v01.z *= rzB; v01.w *= rzB;
      *p00 = v00; *p01 = v01;
    }
  }

  // final output
  {
    const float rz0 = sm.rZs[r0], rz1 = sm.rZs[r1];
#pragma unroll
    for (int j = 0; j < 4; ++j) {
      const int c = 32 * wc + 8 * j + 2 * tig;
      const float vs0 = sm.Vcsum[c], vs1 = sm.Vcsum[c + 1];
      float2 o0 = make_float2(rz0 * (oacc[j][0] + vs0), rz0 * (oacc[j][1] + vs1));
      float2 o1 = make_float2(rz1 * (oacc[j][2] + vs0), rz1 * (oacc[j][3] + vs1));
      *reinterpret_cast<float2*>(&outb[(size_t)(q0 + r0) * kD + c]) = o0;
      *reinterpret_cast<float2*>(&outb[(size_t)(q0 + r1) * kD + c]) = o1;
    }
  }
}

extern "C" void kernel_launch(void* const* d_in, const int* in_sizes, int n_in,
                              void* d_out, int out_size) {
  (void)in_sizes; (void)n_in; (void)out_size;
  const float* Q = (const float*)d_in[0];
  const float* K = (const float*)d_in[1];
  const float* V = (const float*)d_in[2];
  float* out  = (float*)d_out;
  float* attn = out + (size_t)kB * kS * kD;

  cudaFuncSetAttribute(sdpa_kernel, cudaFuncAttributeMaxDynamicSharedMemorySize,
                       SMEM_BYTES);
  dim3 grid(NKT, kB);
  sdpa_kernel<<<grid, NT, SMEM_BYTES>>>(Q, K, V, out, attn);
}